// round 12
// baseline (speedup 1.0000x reference)
#include <cuda_runtime.h>
#include <cstdint>

// Problem dims
#define CI    32
#define HW    56
#define CO    64
#define KK    288          // CI*3*3
#define LL    3136         // 56*56
#define ROWS  200704       // CO*LL
#define NP    57802752     // ROWS*KK

// flip iff (bits64 >> 12) < MTH  <=>  bits64 < (MTH << 12)   (integer-exact)
#define MTH   36028797018964ULL
#define CTH   (MTH << 12)

// Scratch (device globals: no allocations allowed)
__device__ float    g_wq[CO * KK];
__device__ float    g_c[NP];          // 231 MB cumsum storage
__device__ float    g_y[ROWS];
__device__ unsigned g_maxp, g_maxc, g_maxy;
__device__ uint2    g_keys[6];        // (ku, klo) for P, C, Y stages
__device__ int2     g_tab[KK];        // per-k: x-offset delta, (ki<<8)|kj

// ---------------- Threefry2x32 (exact JAX rotation/key schedule) ----------------
__device__ __forceinline__ void tf2x32(uint32_t k0, uint32_t k1,
                                       uint32_t x0, uint32_t x1,
                                       uint32_t& o0, uint32_t& o1) {
    uint32_t ks2 = k0 ^ k1 ^ 0x1BD11BDAu;
#define TFR(r) { x0 += x1; x1 = __funnelshift_l(x1, x1, (r)); x1 ^= x0; }
    x0 += k0; x1 += k1;
    TFR(13) TFR(15) TFR(26) TFR(6)
    x0 += k1;  x1 += ks2 + 1u;
    TFR(17) TFR(29) TFR(16) TFR(24)
    x0 += ks2; x1 += k0 + 2u;
    TFR(13) TFR(15) TFR(26) TFR(6)
    x0 += k0;  x1 += k1 + 3u;
    TFR(17) TFR(29) TFR(16) TFR(24)
    x0 += k1;  x1 += ks2 + 4u;
    TFR(13) TFR(15) TFR(26) TFR(6)
    x0 += ks2; x1 += k0 + 5u;
#undef TFR
    o0 = x0; o1 = x1;
}

// u-draw: flip decision only. bits64 < CTH  ==  (bits64>>12) < MTH  ==  u_f64 < 0.008
__device__ __forceinline__ bool flip_draw(uint2 ku, uint32_t idx) {
    uint32_t ua, ub;
    tf2x32(ku.x, ku.y, 0u, idx, ua, ub);
    return (((uint64_t)ua << 32) | (uint64_t)ub) < CTH;
}
// pos-draw: mask bit (int64 randint % 8 -> low word & 7)
__device__ __forceinline__ int pos_mask(uint2 klo, uint32_t idx) {
    uint32_t pa, pb;
    tf2x32(klo.x, klo.y, 0u, idx, pa, pb);
    return 1 << (int)(pb & 7u);
}

// Exact RN(x/s) in 3 ops given r = RN(1/s) (Markstein; fma required).
__device__ __forceinline__ float div_exact(float x, float s, float r) {
    float q0 = __fmul_rn(x, r);
    float e  = __fmaf_rn(-s, q0, x);
    return __fmaf_rn(e, r, q0);
}

// Flip-free quant+STE. Clamp removed: scale = max|x|/127+1e-12 => |x/scale| < 127,
// so rint(t) in [-127,127] always; [-128,127] clip is an identity. Then qf=q&255
// sign-extends back to q, so qs == r exactly.
__device__ __forceinline__ float quant_noflip(float x, float scale, float rcp) {
    float t = div_exact(x, scale, rcp);
    float r = rintf(t);
    float y = __fmul_rn(r, scale);
    return __fadd_rn(x, __fsub_rn(y, x));
}
// Quant+STE with flip mask m (m may be 0 -> identical to noflip). Same dead-clamp arg.
__device__ __forceinline__ float quant_flip(float x, float scale, float rcp, int m) {
    float t = div_exact(x, scale, rcp);
    float r = rintf(t);
    int qf = ((int)r & 255) ^ m;
    float qs = (float)(signed char)(qf);        // two's-complement view
    float y  = __fmul_rn(qs, scale);
    return __fadd_rn(x, __fsub_rn(y, x));
}

__device__ __forceinline__ float get_scale(const unsigned* bits) {
    return __fadd_rn(__fdiv_rn(__uint_as_float(*bits), 127.0f), 1e-12f);
}

// ---------------- K0: reset accumulators, subkeys, per-k table ----------------
__global__ void k_init() {
    g_maxp = 0u; g_maxc = 0u; g_maxy = 0u;
    uint2 ks[3];
    for (uint32_t i = 0; i < 3; i++) tf2x32(0u, 42u, 0u, i, ks[i].x, ks[i].y);
    for (int i = 0; i < 3; i++) {
        uint2 ku, kr, klo;
        tf2x32(ks[i].x, ks[i].y, 0u, 0u, ku.x, ku.y);   // split(k)[0] -> uniform key
        tf2x32(ks[i].x, ks[i].y, 0u, 1u, kr.x, kr.y);   // split(k)[1] -> randint key
        tf2x32(kr.x,    kr.y,    0u, 1u, klo.x, klo.y); // split(kr)[1] -> lower_bits key
        g_keys[2 * i]     = ku;
        g_keys[2 * i + 1] = klo;
    }
    for (int k = 0; k < KK; k++) {
        int c = k / 9, t = k % 9, ki = t / 3, kj = t % 3;
        g_tab[k].x = c * (HW * HW) + ki * HW + kj;   // + (oh-1)*56 + (ow-1) at use
        g_tab[k].y = (ki << 8) | kj;
    }
}

// ---------------- K1: weight quantization (quant_ste) ----------------
__global__ void k_wq(const float* __restrict__ w) {
    __shared__ float red[256];
    __shared__ float s_scale;
    float m = 0.0f;
    for (int i = threadIdx.x; i < CO * KK; i += 256) m = fmaxf(m, fabsf(w[i]));
    red[threadIdx.x] = m; __syncthreads();
    for (int s = 128; s > 0; s >>= 1) {
        if (threadIdx.x < s) red[threadIdx.x] = fmaxf(red[threadIdx.x], red[threadIdx.x + s]);
        __syncthreads();
    }
    if (threadIdx.x == 0) s_scale = __fadd_rn(__fdiv_rn(red[0], 127.0f), 1e-12f);
    __syncthreads();
    float sc = s_scale;
    for (int i = threadIdx.x; i < CO * KK; i += 256) {
        float ww = w[i];
        float r  = rintf(__fdiv_rn(ww, sc));
        r = fminf(127.0f, fmaxf(-128.0f, r));
        float q  = __fmul_rn(r, sc);
        g_wq[i]  = __fadd_rn(ww, __fsub_rn(q, ww));   // STE forward, literal
    }
}

// ---------------- K2: max|p| = max_k( max_l|xcol| * max_co|wq| ) ----------------
__global__ void k_scalep(const float* __restrict__ x) {
    int k = blockIdx.x;
    int c = k / 9, t = k % 9, ki = t / 3, kj = t % 3;
    __shared__ float red[128];
    float m = 0.0f;
    for (int l = threadIdx.x; l < LL; l += 128) {
        int oh = l / HW, ow = l % HW;
        int ih = oh + ki - 1, iw = ow + kj - 1;
        float v = 0.0f;
        if ((unsigned)ih < HW && (unsigned)iw < HW) v = x[(c * HW + ih) * HW + iw];
        m = fmaxf(m, fabsf(v));
    }
    red[threadIdx.x] = m; __syncthreads();
    for (int s = 64; s > 0; s >>= 1) {
        if (threadIdx.x < s) red[threadIdx.x] = fmaxf(red[threadIdx.x], red[threadIdx.x + s]);
        __syncthreads();
    }
    if (threadIdx.x == 0) {
        float wm = 0.0f;
        for (int co = 0; co < CO; co++) wm = fmaxf(wm, fabsf(g_wq[co * KK + k]));
        float p = __fmul_rn(red[0], wm);   // exact: fp mul rounding is monotone
        atomicMax(&g_maxp, __float_as_uint(p));
    }
}

// ---------------- K3: warp-per-row: deferred-flip bitflip + exact scan + fused store ----------------
__global__ void __launch_bounds__(128) k_main(const float* __restrict__ x) {
    const int wid = threadIdx.x >> 5;
    const int lid = threadIdx.x & 31;
    const int r   = blockIdx.x * 4 + wid;
    const int co = r / LL, l = r % LL;
    const int oh = l / HW, ow = l % HW;
    __shared__ __align__(16) float lv_all[4][576];  // levels: 288+144+72+36+18+9+4+2+1
    float* lv = lv_all[wid];

    const float scale_p = get_scale(&g_maxp);
    const float rcp_p   = __frcp_rn(scale_p);
    const uint2 ku  = g_keys[0];
    const uint2 klo = g_keys[1];
    const float* wrow = g_wq + co * KK;
    const int base = (oh - 1) * HW + (ow - 1);
    const bool interior = (oh >= 1 && oh < HW - 1 && ow >= 1 && ow < HW - 1);
    const uint32_t ridx = (uint32_t)r * (uint32_t)KK;

    // ---- main pass: u-draw + flip-free quant; keep p in regs; record flip mask ----
    float pv[9];
    unsigned fmask = 0u;
    if (interior) {
        #pragma unroll
        for (int i = 0; i < 9; i++) {
            int k = i * 32 + lid;
            pv[i] = __fmul_rn(x[base + g_tab[k].x], wrow[k]);
            if (flip_draw(ku, ridx + (uint32_t)k)) fmask |= (1u << i);
            lv[k] = quant_noflip(pv[i], scale_p, rcp_p);
        }
    } else {
        #pragma unroll
        for (int i = 0; i < 9; i++) {
            int k = i * 32 + lid;
            int2 tv = g_tab[k];
            int ki = tv.y >> 8, kj = tv.y & 255;
            float xv = 0.0f;
            if ((unsigned)(oh - 1 + ki) < HW && (unsigned)(ow - 1 + kj) < HW)
                xv = x[base + tv.x];
            pv[i] = __fmul_rn(xv, wrow[k]);
            if (flip_draw(ku, ridx + (uint32_t)k)) fmask |= (1u << i);
            lv[k] = quant_noflip(pv[i], scale_p, rcp_p);
        }
    }
    // ---- fix-up: rare flips (E ~2.3 per row-warp); static unroll, reg-cached p ----
    if (__any_sync(0xffffffffu, fmask != 0u)) {
        #pragma unroll
        for (int i = 0; i < 9; i++) {
            if (fmask & (1u << i)) {
                int k = i * 32 + lid;
                int m = pos_mask(klo, ridx + (uint32_t)k);
                lv[k] = quant_flip(pv[i], scale_p, rcp_p, m);
            }
        }
    }
    __syncwarp();

    // ---- up-sweep (exact jax associative_scan tree), float2 reads ----
    const float2* lv2 = (const float2*)lv;
    for (int i = lid; i < 144; i += 32) {            // t=0: 288->144
        float2 v = lv2[i];
        lv[288 + i] = __fadd_rn(v.x, v.y);
    }
    __syncwarp();
    for (int i = lid; i < 72; i += 32) {             // t=1: 144->72
        float2 v = lv2[144 + i];
        lv[432 + i] = __fadd_rn(v.x, v.y);
    }
    __syncwarp();
    for (int i = lid; i < 36; i += 32) {             // t=2: 72->36
        float2 v = lv2[216 + i];
        lv[504 + i] = __fadd_rn(v.x, v.y);
    }
    __syncwarp();
    if (lid < 18) lv[540 + lid] = __fadd_rn(lv[504 + 2 * lid], lv[504 + 2 * lid + 1]);
    __syncwarp();
    if (lid < 9)  lv[558 + lid] = __fadd_rn(lv[540 + 2 * lid], lv[540 + 2 * lid + 1]);
    __syncwarp();
    if (lid < 4)  lv[567 + lid] = __fadd_rn(lv[558 + 2 * lid], lv[558 + 2 * lid + 1]);
    __syncwarp();
    if (lid < 2)  lv[571 + lid] = __fadd_rn(lv[567 + 2 * lid], lv[567 + 2 * lid + 1]);
    __syncwarp();
    if (lid < 1)  lv[573] = __fadd_rn(lv[571], lv[572]);
    __syncwarp();

    // ---- down-sweep: s[2i+1]=child[i], s[2i+2]=child[i]+x[2i+2] ----
    if (lid < 1) lv[572] = lv[573];                  // t=7: n=2
    __syncwarp();
    if (lid < 2) {                                   // t=6: n=4, OFF=567, up=571
        float sc = lv[571 + lid];
        bool has = (2 * lid + 2 < 4);
        float ev = has ? __fadd_rn(sc, lv[567 + 2 * lid + 2]) : 0.0f;
        lv[567 + 2 * lid + 1] = sc;
        if (has) lv[567 + 2 * lid + 2] = ev;
    }
    __syncwarp();
    if (lid < 4) {                                   // t=5: n=9, OFF=558, up=567
        float sc = lv[567 + lid];
        bool has = (2 * lid + 2 < 9);
        float ev = has ? __fadd_rn(sc, lv[558 + 2 * lid + 2]) : 0.0f;
        lv[558 + 2 * lid + 1] = sc;
        if (has) lv[558 + 2 * lid + 2] = ev;
    }
    __syncwarp();
    if (lid < 9) {                                   // t=4: n=18, OFF=540, up=558
        float sc = lv[558 + lid];
        bool has = (2 * lid + 2 < 18);
        float ev = has ? __fadd_rn(sc, lv[540 + 2 * lid + 2]) : 0.0f;
        lv[540 + 2 * lid + 1] = sc;
        if (has) lv[540 + 2 * lid + 2] = ev;
    }
    __syncwarp();
    if (lid < 18) {                                  // t=3: n=36, OFF=504, up=540
        float sc = lv[540 + lid];
        bool has = (2 * lid + 2 < 36);
        float ev = has ? __fadd_rn(sc, lv[504 + 2 * lid + 2]) : 0.0f;
        lv[504 + 2 * lid + 1] = sc;
        if (has) lv[504 + 2 * lid + 2] = ev;
    }
    __syncwarp();
    for (int i = lid; i < 36; i += 32) {             // t=2: n=72, OFF=432, up=504
        float sc = lv[504 + i];
        bool has = (2 * i + 2 < 72);
        float ev = has ? __fadd_rn(sc, lv[432 + 2 * i + 2]) : 0.0f;
        lv[432 + 2 * i + 1] = sc;
        if (has) lv[432 + 2 * i + 2] = ev;
    }
    __syncwarp();
    for (int i = lid; i < 72; i += 32) {             // t=1: n=144, OFF=288, up=432
        float sc = lv[432 + i];
        bool has = (2 * i + 2 < 144);
        float ev = has ? __fadd_rn(sc, lv[288 + 2 * i + 2]) : 0.0f;
        lv[288 + 2 * i + 1] = sc;
        if (has) lv[288 + 2 * i + 2] = ev;
    }
    __syncwarp();

    // ---- final level fused with gmem store + max|c| ----
    // c[0]=x0[0]; c[2i+1]=s1[i]; c[2i+2]=s1[i]+x0[2i+2]
    float* crow = g_c + (size_t)r * KK;
    float m = 0.0f;
    for (int i = lid; i < 144; i += 32) {
        float sc = lv[288 + i];
        crow[2 * i + 1] = sc; m = fmaxf(m, fabsf(sc));
        if (i == 0) { float c0 = lv[0]; crow[0] = c0; m = fmaxf(m, fabsf(c0)); }
        if (2 * i + 2 < KK) {
            float ev = __fadd_rn(sc, lv[2 * i + 2]);
            crow[2 * i + 2] = ev; m = fmaxf(m, fabsf(ev));
        }
    }
    #pragma unroll
    for (int d = 16; d > 0; d >>= 1)
        m = fmaxf(m, __shfl_xor_sync(0xffffffffu, m, d));
    if (lid == 0) atomicMax(&g_maxc, __float_as_uint(m));
}

// ---------------- K4: warp-per-row: c_fi, y = c_fi[287] + sum_{k=1..286}(c_fi - c) ----------------
// Deferred flips: in-loop accumulates only unflipped terms; flipped terms added in
// a statically unrolled fix-up using register-cached c values.
__global__ void __launch_bounds__(128) k_yrow() {
    const int wid = threadIdx.x >> 5;
    const int lid = threadIdx.x & 31;
    const int r   = blockIdx.x * 4 + wid;

    const float scale_c = get_scale(&g_maxc);
    const float rcp_c   = __frcp_rn(scale_c);
    const uint2 ku  = g_keys[2];
    const uint2 klo = g_keys[3];
    const uint32_t ridx = (uint32_t)r * (uint32_t)KK;
    const float* crow = g_c + (size_t)r * KK;

    float cv[9];
    float acc = 0.0f;
    float last = 0.0f;
    unsigned fmask = 0u;
    #pragma unroll
    for (int i = 0; i < 9; i++) {
        int k = i * 32 + lid;
        cv[i] = crow[k];
        bool flip = flip_draw(ku, ridx + (uint32_t)k);
        if (flip) fmask |= (1u << i);
        float cf = quant_noflip(cv[i], scale_c, rcp_c);
        if (!flip) {
            if (k == KK - 1) last = cf;                     // lane 31, iter 8
            else if (k > 0) acc = __fadd_rn(acc, __fsub_rn(cf, cv[i]));
        }
    }
    if (__any_sync(0xffffffffu, fmask != 0u)) {
        #pragma unroll
        for (int i = 0; i < 9; i++) {
            if (fmask & (1u << i)) {
                int k = i * 32 + lid;
                int m = pos_mask(klo, ridx + (uint32_t)k);
                float cf = quant_flip(cv[i], scale_c, rcp_c, m);
                if (k == KK - 1) last = cf;
                else if (k > 0) acc = __fadd_rn(acc, __fsub_rn(cf, cv[i]));
            }
        }
    }
    #pragma unroll
    for (int d = 16; d > 0; d >>= 1)
        acc = __fadd_rn(acc, __shfl_xor_sync(0xffffffffu, acc, d));
    last = __shfl_sync(0xffffffffu, last, 31);
    if (lid == 0) {
        float y = __fadd_rn(last, acc);
        g_y[r] = y;
        atomicMax(&g_maxy, __float_as_uint(fabsf(y)));
    }
}

// ---------------- K5: final output bitflip (ROWS = 784*256 exactly, all warps full) ----------------
__global__ void k_out(float* __restrict__ out) {
    int i = blockIdx.x * 256 + threadIdx.x;
    const float scale_y = get_scale(&g_maxy);
    const float rcp_y   = __frcp_rn(scale_y);
    float v = g_y[i];
    bool flip = flip_draw(g_keys[4], (uint32_t)i);
    float o;
    if (__ballot_sync(0xffffffffu, flip)) {
        int m = flip ? pos_mask(g_keys[5], (uint32_t)i) : 0;
        o = quant_flip(v, scale_y, rcp_y, m);       // m=0 path == noflip exactly
    } else {
        o = quant_noflip(v, scale_y, rcp_y);
    }
    out[i] = o;
}

// ---------------- launch ----------------
extern "C" void kernel_launch(void* const* d_in, const int* in_sizes, int n_in,
                              void* d_out, int out_size) {
    const float* x = (const float*)d_in[0];
    const float* w = (const float*)d_in[1];
    if (n_in >= 2 && in_sizes[0] == CO * KK && in_sizes[1] == CI * HW * HW) {
        const float* tmp = x; x = w; w = tmp;
    }
    k_init<<<1, 1>>>();
    k_wq<<<1, 256>>>(w);
    k_scalep<<<KK, 128>>>(x);
    k_main<<<ROWS / 4, 128>>>(x);
    k_yrow<<<ROWS / 4, 128>>>();
    k_out<<<ROWS / 256, 256>>>((float*)d_out);
}

// round 13
// speedup vs baseline: 1.0617x; 1.0617x over previous
#include <cuda_runtime.h>
#include <cstdint>

// Problem dims
#define CI    32
#define HW    56
#define CO    64
#define KK    288          // CI*3*3
#define LL    3136         // 56*56
#define ROWS  200704       // CO*LL
#define NP    57802752     // ROWS*KK

// flip iff (bits64 >> 12) < MTH  <=>  bits64 < (MTH << 12)   (integer-exact)
#define MTH   36028797018964ULL
#define CTH   (MTH << 12)

// Scratch (device globals: no allocations allowed)
__device__ float    g_wq[CO * KK];
__device__ float    g_c[NP];          // 231 MB cumsum storage
__device__ float    g_y[ROWS];
__device__ unsigned g_maxp, g_maxc, g_maxy;
__device__ uint2    g_keys[6];        // (ku, klo) for P, C, Y stages
__device__ int2     g_tab[KK];        // per-k: x-offset delta, (ki<<8)|kj

// ---------------- Threefry2x32 (exact JAX rotation/key schedule) ----------------
__device__ __forceinline__ void tf2x32(uint32_t k0, uint32_t k1,
                                       uint32_t x0, uint32_t x1,
                                       uint32_t& o0, uint32_t& o1) {
    uint32_t ks2 = k0 ^ k1 ^ 0x1BD11BDAu;
#define TFR(r) { x0 += x1; x1 = __funnelshift_l(x1, x1, (r)); x1 ^= x0; }
    x0 += k0; x1 += k1;
    TFR(13) TFR(15) TFR(26) TFR(6)
    x0 += k1;  x1 += ks2 + 1u;
    TFR(17) TFR(29) TFR(16) TFR(24)
    x0 += ks2; x1 += k0 + 2u;
    TFR(13) TFR(15) TFR(26) TFR(6)
    x0 += k0;  x1 += k1 + 3u;
    TFR(17) TFR(29) TFR(16) TFR(24)
    x0 += k1;  x1 += ks2 + 4u;
    TFR(13) TFR(15) TFR(26) TFR(6)
    x0 += ks2; x1 += k0 + 5u;
#undef TFR
    o0 = x0; o1 = x1;
}

// u-draw: flip decision only. bits64 < CTH  ==  (bits64>>12) < MTH  ==  u_f64 < 0.008
__device__ __forceinline__ bool flip_draw(uint2 ku, uint32_t idx) {
    uint32_t ua, ub;
    tf2x32(ku.x, ku.y, 0u, idx, ua, ub);
    return (((uint64_t)ua << 32) | (uint64_t)ub) < CTH;
}
// pos-draw: mask bit (int64 randint % 8 -> low word & 7)
__device__ __forceinline__ int pos_mask(uint2 klo, uint32_t idx) {
    uint32_t pa, pb;
    tf2x32(klo.x, klo.y, 0u, idx, pa, pb);
    return 1 << (int)(pb & 7u);
}

// Exact RN(x/s) in 3 ops given r = RN(1/s) (Markstein; fma required).
__device__ __forceinline__ float div_exact(float x, float s, float r) {
    float q0 = __fmul_rn(x, r);
    float e  = __fmaf_rn(-s, q0, x);
    return __fmaf_rn(e, r, q0);
}

// Flip-free quant+STE. Clamp removed: scale = max|x|/127+1e-12 => |x/scale| < 127,
// so rint(t) in [-127,127] always; [-128,127] clip is an identity. Then qf=q&255
// sign-extends back to q, so qs == r exactly.
__device__ __forceinline__ float quant_noflip(float x, float scale, float rcp) {
    float t = div_exact(x, scale, rcp);
    float r = rintf(t);
    float y = __fmul_rn(r, scale);
    return __fadd_rn(x, __fsub_rn(y, x));
}
// Quant+STE with flip mask m (m may be 0 -> identical to noflip). Same dead-clamp arg.
__device__ __forceinline__ float quant_flip(float x, float scale, float rcp, int m) {
    float t = div_exact(x, scale, rcp);
    float r = rintf(t);
    int qf = ((int)r & 255) ^ m;
    float qs = (float)(signed char)(qf);        // two's-complement view
    float y  = __fmul_rn(qs, scale);
    return __fadd_rn(x, __fsub_rn(y, x));
}

__device__ __forceinline__ float get_scale(const unsigned* bits) {
    return __fadd_rn(__fdiv_rn(__uint_as_float(*bits), 127.0f), 1e-12f);
}

// ---------------- K0: reset accumulators, subkeys, per-k table ----------------
__global__ void k_init() {
    g_maxp = 0u; g_maxc = 0u; g_maxy = 0u;
    uint2 ks[3];
    for (uint32_t i = 0; i < 3; i++) tf2x32(0u, 42u, 0u, i, ks[i].x, ks[i].y);
    for (int i = 0; i < 3; i++) {
        uint2 ku, kr, klo;
        tf2x32(ks[i].x, ks[i].y, 0u, 0u, ku.x, ku.y);   // split(k)[0] -> uniform key
        tf2x32(ks[i].x, ks[i].y, 0u, 1u, kr.x, kr.y);   // split(k)[1] -> randint key
        tf2x32(kr.x,    kr.y,    0u, 1u, klo.x, klo.y); // split(kr)[1] -> lower_bits key
        g_keys[2 * i]     = ku;
        g_keys[2 * i + 1] = klo;
    }
    for (int k = 0; k < KK; k++) {
        int c = k / 9, t = k % 9, ki = t / 3, kj = t % 3;
        g_tab[k].x = c * (HW * HW) + ki * HW + kj;   // + (oh-1)*56 + (ow-1) at use
        g_tab[k].y = (ki << 8) | kj;
    }
}

// ---------------- K1: weight quantization (quant_ste) ----------------
__global__ void k_wq(const float* __restrict__ w) {
    __shared__ float red[256];
    __shared__ float s_scale;
    float m = 0.0f;
    for (int i = threadIdx.x; i < CO * KK; i += 256) m = fmaxf(m, fabsf(w[i]));
    red[threadIdx.x] = m; __syncthreads();
    for (int s = 128; s > 0; s >>= 1) {
        if (threadIdx.x < s) red[threadIdx.x] = fmaxf(red[threadIdx.x], red[threadIdx.x + s]);
        __syncthreads();
    }
    if (threadIdx.x == 0) s_scale = __fadd_rn(__fdiv_rn(red[0], 127.0f), 1e-12f);
    __syncthreads();
    float sc = s_scale;
    for (int i = threadIdx.x; i < CO * KK; i += 256) {
        float ww = w[i];
        float r  = rintf(__fdiv_rn(ww, sc));
        r = fminf(127.0f, fmaxf(-128.0f, r));
        float q  = __fmul_rn(r, sc);
        g_wq[i]  = __fadd_rn(ww, __fsub_rn(q, ww));   // STE forward, literal
    }
}

// ---------------- K2: max|p| = max_k( max_l|xcol| * max_co|wq| ) ----------------
__global__ void k_scalep(const float* __restrict__ x) {
    int k = blockIdx.x;
    int c = k / 9, t = k % 9, ki = t / 3, kj = t % 3;
    __shared__ float red[128];
    float m = 0.0f;
    for (int l = threadIdx.x; l < LL; l += 128) {
        int oh = l / HW, ow = l % HW;
        int ih = oh + ki - 1, iw = ow + kj - 1;
        float v = 0.0f;
        if ((unsigned)ih < HW && (unsigned)iw < HW) v = x[(c * HW + ih) * HW + iw];
        m = fmaxf(m, fabsf(v));
    }
    red[threadIdx.x] = m; __syncthreads();
    for (int s = 64; s > 0; s >>= 1) {
        if (threadIdx.x < s) red[threadIdx.x] = fmaxf(red[threadIdx.x], red[threadIdx.x + s]);
        __syncthreads();
    }
    if (threadIdx.x == 0) {
        float wm = 0.0f;
        for (int co = 0; co < CO; co++) wm = fmaxf(wm, fabsf(g_wq[co * KK + k]));
        float p = __fmul_rn(red[0], wm);   // exact: fp mul rounding is monotone
        atomicMax(&g_maxp, __float_as_uint(p));
    }
}

// p(k) loader shared by main loop and fix-up
__device__ __forceinline__ float load_p(const float* __restrict__ x,
                                        const float* __restrict__ wrow,
                                        int base, int oh, int ow, bool interior, int k) {
    int2 tv = g_tab[k];
    float xv = 0.0f;
    if (interior) {
        xv = x[base + tv.x];
    } else {
        int ki = tv.y >> 8, kj = tv.y & 255;
        if ((unsigned)(oh - 1 + ki) < HW && (unsigned)(ow - 1 + kj) < HW)
            xv = x[base + tv.x];
    }
    return __fmul_rn(xv, wrow[k]);
}

// ---------------- K3: warp-per-row: deferred-flip bitflip + exact scan + fused store ----------------
__global__ void __launch_bounds__(128) k_main(const float* __restrict__ x) {
    const int wid = threadIdx.x >> 5;
    const int lid = threadIdx.x & 31;
    const int r   = blockIdx.x * 4 + wid;
    const int co = r / LL, l = r % LL;
    const int oh = l / HW, ow = l % HW;
    __shared__ __align__(16) float lv_all[4][576];  // levels: 288+144+72+36+18+9+4+2+1
    float* lv = lv_all[wid];

    const float scale_p = get_scale(&g_maxp);
    const float rcp_p   = __frcp_rn(scale_p);
    const uint2 ku  = g_keys[0];
    const uint2 klo = g_keys[1];
    const float* wrow = g_wq + co * KK;
    const int base = (oh - 1) * HW + (ow - 1);
    const bool interior = (oh >= 1 && oh < HW - 1 && ow >= 1 && ow < HW - 1);
    const uint32_t ridx = (uint32_t)r * (uint32_t)KK;

    // ---- main pass: u-draw + flip-free quant; record flip mask ----
    unsigned fmask = 0u;
    if (interior) {
        #pragma unroll
        for (int i = 0; i < 9; i++) {
            int k = i * 32 + lid;
            float p = __fmul_rn(x[base + g_tab[k].x], wrow[k]);
            if (flip_draw(ku, ridx + (uint32_t)k)) fmask |= (1u << i);
            lv[k] = quant_noflip(p, scale_p, rcp_p);
        }
    } else {
        #pragma unroll
        for (int i = 0; i < 9; i++) {
            int k = i * 32 + lid;
            float p = load_p(x, wrow, base, oh, ow, false, k);
            if (flip_draw(ku, ridx + (uint32_t)k)) fmask |= (1u << i);
            lv[k] = quant_noflip(p, scale_p, rcp_p);
        }
    }
    // ---- fix-up: rare flips (E ~2.3 per row-warp), compact single region ----
    while (__any_sync(0xffffffffu, fmask != 0u)) {
        if (fmask) {
            int i = __ffs(fmask) - 1; fmask &= fmask - 1u;
            int k = i * 32 + lid;
            float p = load_p(x, wrow, base, oh, ow, interior, k);
            int m = pos_mask(klo, ridx + (uint32_t)k);
            lv[k] = quant_flip(p, scale_p, rcp_p, m);
        }
    }
    __syncwarp();

    // ---- up-sweep (exact jax associative_scan tree), float2 reads ----
    const float2* lv2 = (const float2*)lv;
    for (int i = lid; i < 144; i += 32) {            // t=0: 288->144
        float2 v = lv2[i];
        lv[288 + i] = __fadd_rn(v.x, v.y);
    }
    __syncwarp();
    for (int i = lid; i < 72; i += 32) {             // t=1: 144->72
        float2 v = lv2[144 + i];
        lv[432 + i] = __fadd_rn(v.x, v.y);
    }
    __syncwarp();
    for (int i = lid; i < 36; i += 32) {             // t=2: 72->36
        float2 v = lv2[216 + i];
        lv[504 + i] = __fadd_rn(v.x, v.y);
    }
    __syncwarp();
    if (lid < 18) lv[540 + lid] = __fadd_rn(lv[504 + 2 * lid], lv[504 + 2 * lid + 1]);
    __syncwarp();
    if (lid < 9)  lv[558 + lid] = __fadd_rn(lv[540 + 2 * lid], lv[540 + 2 * lid + 1]);
    __syncwarp();
    if (lid < 4)  lv[567 + lid] = __fadd_rn(lv[558 + 2 * lid], lv[558 + 2 * lid + 1]);
    __syncwarp();
    if (lid < 2)  lv[571 + lid] = __fadd_rn(lv[567 + 2 * lid], lv[567 + 2 * lid + 1]);
    __syncwarp();
    if (lid < 1)  lv[573] = __fadd_rn(lv[571], lv[572]);
    __syncwarp();

    // ---- down-sweep: s[2i+1]=child[i], s[2i+2]=child[i]+x[2i+2] ----
    if (lid < 1) lv[572] = lv[573];                  // t=7: n=2
    __syncwarp();
    if (lid < 2) {                                   // t=6: n=4, OFF=567, up=571
        float sc = lv[571 + lid];
        bool has = (2 * lid + 2 < 4);
        float ev = has ? __fadd_rn(sc, lv[567 + 2 * lid + 2]) : 0.0f;
        lv[567 + 2 * lid + 1] = sc;
        if (has) lv[567 + 2 * lid + 2] = ev;
    }
    __syncwarp();
    if (lid < 4) {                                   // t=5: n=9, OFF=558, up=567
        float sc = lv[567 + lid];
        bool has = (2 * lid + 2 < 9);
        float ev = has ? __fadd_rn(sc, lv[558 + 2 * lid + 2]) : 0.0f;
        lv[558 + 2 * lid + 1] = sc;
        if (has) lv[558 + 2 * lid + 2] = ev;
    }
    __syncwarp();
    if (lid < 9) {                                   // t=4: n=18, OFF=540, up=558
        float sc = lv[558 + lid];
        bool has = (2 * lid + 2 < 18);
        float ev = has ? __fadd_rn(sc, lv[540 + 2 * lid + 2]) : 0.0f;
        lv[540 + 2 * lid + 1] = sc;
        if (has) lv[540 + 2 * lid + 2] = ev;
    }
    __syncwarp();
    if (lid < 18) {                                  // t=3: n=36, OFF=504, up=540
        float sc = lv[540 + lid];
        bool has = (2 * lid + 2 < 36);
        float ev = has ? __fadd_rn(sc, lv[504 + 2 * lid + 2]) : 0.0f;
        lv[504 + 2 * lid + 1] = sc;
        if (has) lv[504 + 2 * lid + 2] = ev;
    }
    __syncwarp();
    for (int i = lid; i < 36; i += 32) {             // t=2: n=72, OFF=432, up=504
        float sc = lv[504 + i];
        bool has = (2 * i + 2 < 72);
        float ev = has ? __fadd_rn(sc, lv[432 + 2 * i + 2]) : 0.0f;
        lv[432 + 2 * i + 1] = sc;
        if (has) lv[432 + 2 * i + 2] = ev;
    }
    __syncwarp();
    for (int i = lid; i < 72; i += 32) {             // t=1: n=144, OFF=288, up=432
        float sc = lv[432 + i];
        bool has = (2 * i + 2 < 144);
        float ev = has ? __fadd_rn(sc, lv[288 + 2 * i + 2]) : 0.0f;
        lv[288 + 2 * i + 1] = sc;
        if (has) lv[288 + 2 * i + 2] = ev;
    }
    __syncwarp();

    // ---- final level fused with gmem store + max|c| ----
    // c[0]=x0[0]; c[2i+1]=s1[i]; c[2i+2]=s1[i]+x0[2i+2]
    float* crow = g_c + (size_t)r * KK;
    float m = 0.0f;
    for (int i = lid; i < 144; i += 32) {
        float sc = lv[288 + i];
        crow[2 * i + 1] = sc; m = fmaxf(m, fabsf(sc));
        if (i == 0) { float c0 = lv[0]; crow[0] = c0; m = fmaxf(m, fabsf(c0)); }
        if (2 * i + 2 < KK) {
            float ev = __fadd_rn(sc, lv[2 * i + 2]);
            crow[2 * i + 2] = ev; m = fmaxf(m, fabsf(ev));
        }
    }
    #pragma unroll
    for (int d = 16; d > 0; d >>= 1)
        m = fmaxf(m, __shfl_xor_sync(0xffffffffu, m, d));
    if (lid == 0) atomicMax(&g_maxc, __float_as_uint(m));
}

// ---------------- K4: warp-per-row: c_fi, y = c_fi[287] + sum_{k=1..286}(c_fi - c) ----------------
// Deferred flips: in-loop accumulates only unflipped terms; flipped terms added in
// a compact while-loop fix-up (reloads c from gmem -> no register caching pressure).
__global__ void __launch_bounds__(128) k_yrow() {
    const int wid = threadIdx.x >> 5;
    const int lid = threadIdx.x & 31;
    const int r   = blockIdx.x * 4 + wid;

    const float scale_c = get_scale(&g_maxc);
    const float rcp_c   = __frcp_rn(scale_c);
    const uint2 ku  = g_keys[2];
    const uint2 klo = g_keys[3];
    const uint32_t ridx = (uint32_t)r * (uint32_t)KK;
    const float* crow = g_c + (size_t)r * KK;

    float acc = 0.0f;
    float last = 0.0f;
    unsigned fmask = 0u;
    #pragma unroll
    for (int i = 0; i < 9; i++) {
        int k = i * 32 + lid;
        float cv = crow[k];
        bool flip = flip_draw(ku, ridx + (uint32_t)k);
        if (flip) fmask |= (1u << i);
        float cf = quant_noflip(cv, scale_c, rcp_c);
        if (!flip) {
            if (k == KK - 1) last = cf;                     // lane 31, iter 8
            else if (k > 0) acc = __fadd_rn(acc, __fsub_rn(cf, cv));
        }
    }
    while (__any_sync(0xffffffffu, fmask != 0u)) {
        if (fmask) {
            int i = __ffs(fmask) - 1; fmask &= fmask - 1u;
            int k = i * 32 + lid;
            float cv = crow[k];
            int m = pos_mask(klo, ridx + (uint32_t)k);
            float cf = quant_flip(cv, scale_c, rcp_c, m);
            if (k == KK - 1) last = cf;
            else if (k > 0) acc = __fadd_rn(acc, __fsub_rn(cf, cv));
        }
    }
    #pragma unroll
    for (int d = 16; d > 0; d >>= 1)
        acc = __fadd_rn(acc, __shfl_xor_sync(0xffffffffu, acc, d));
    last = __shfl_sync(0xffffffffu, last, 31);
    if (lid == 0) {
        float y = __fadd_rn(last, acc);
        g_y[r] = y;
        atomicMax(&g_maxy, __float_as_uint(fabsf(y)));
    }
}

// ---------------- K5: final output bitflip (ROWS = 784*256 exactly, all warps full) ----------------
__global__ void k_out(float* __restrict__ out) {
    int i = blockIdx.x * 256 + threadIdx.x;
    const float scale_y = get_scale(&g_maxy);
    const float rcp_y   = __frcp_rn(scale_y);
    float v = g_y[i];
    bool flip = flip_draw(g_keys[4], (uint32_t)i);
    float o;
    if (__ballot_sync(0xffffffffu, flip)) {
        int m = flip ? pos_mask(g_keys[5], (uint32_t)i) : 0;
        o = quant_flip(v, scale_y, rcp_y, m);       // m=0 path == noflip exactly
    } else {
        o = quant_noflip(v, scale_y, rcp_y);
    }
    out[i] = o;
}

// ---------------- launch ----------------
extern "C" void kernel_launch(void* const* d_in, const int* in_sizes, int n_in,
                              void* d_out, int out_size) {
    const float* x = (const float*)d_in[0];
    const float* w = (const float*)d_in[1];
    if (n_in >= 2 && in_sizes[0] == CO * KK && in_sizes[1] == CI * HW * HW) {
        const float* tmp = x; x = w; w = tmp;
    }
    k_init<<<1, 1>>>();
    k_wq<<<1, 256>>>(w);
    k_scalep<<<KK, 128>>>(x);
    k_main<<<ROWS / 4, 128>>>(x);
    k_yrow<<<ROWS / 4, 128>>>();
    k_out<<<ROWS / 256, 256>>>((float*)d_out);
}